// round 7
// baseline (speedup 1.0000x reference)
#include <cuda_runtime.h>

// Fixed problem shapes
#define NN   2000                 // nodes per graph
#define EE   32000                // edges (before self loops)
#define ET   (EE + NN)            // 34000 edges incl. self loops
#define GG   32                   // B*D graphs
#define EMBD 32                   // embedding dim
#define HH   4                    // heads
#define HC   128                  // H*C
#define NEG_SLOPE 0.2f
#define CAP  32                   // smem edge-tile capacity (avg deg = 17)
#define GPB  16                   // graphs per block
#define LUTN 2048                 // exp LUT entries over [-16,16), step 1/64
#define LUT_SCALE 64.0f
#define TOKB (NN / 8)             // 250 token blocks
#define CNTB ((ET + 1023) / 1024) // 34 count blocks

// ---- scratch (device globals: no allocation allowed) ----
__device__ float  g_thl[NN * HC];               // 1 MB per-TOKEN features (fp32)
__device__ __align__(16) float g_tas[NN * HH];  // per-token src-logit component
__device__ __align__(16) float g_tad[NN * HH];  // per-token dst-logit component
__device__ int    g_deg[NN];                    // zero-init; scan consumes+resets
__device__ int    g_ofs[NN + 1];
__device__ int    g_fill[NN];
__device__ int    g_csr_src[ET];                // src node per CSR slot (by dst)
__device__ float2 g_lut2[LUTN];                 // (exp_k, exp_{k+1}) pairs

// ------------------------------------------------------------------
// PREP (fully parallel): blocks 0..249 token tables, 250..283 degree
// count (global atomics), 284 exp LUT.
// ------------------------------------------------------------------
__global__ void __launch_bounds__(1024) prep_kernel(
    const int*   __restrict__ adj,
    const float* __restrict__ emb,
    const float* __restrict__ lin_w,
    const float* __restrict__ att_src,
    const float* __restrict__ att_dst)
{
    int tid = threadIdx.x;

    if (blockIdx.x < TOKB) {
        // ---------------- token tables: 8 tokens per block ----------------
        int tok = blockIdx.x * 8 + (tid >> 7);
        int t   = tid & 127;              // output channel 0..127
        const float* er = emb + (size_t)tok * EMBD;

        float acc = 0.f;
#pragma unroll
        for (int k = 0; k < EMBD; k++)
            acc = fmaf(__ldg(er + k), __ldg(lin_w + k * HC + t), acc);

        g_thl[tok * HC + t] = acc;

        int lane = t & 31, h = t >> 5;
        float vs = acc * __ldg(att_src + t);
        float vd = acc * __ldg(att_dst + t);
#pragma unroll
        for (int o = 16; o > 0; o >>= 1) {
            vs += __shfl_xor_sync(0xffffffffu, vs, o);
            vd += __shfl_xor_sync(0xffffffffu, vd, o);
        }
        if (lane == 0) {
            g_tas[tok * HH + h] = vs;
            g_tad[tok * HH + h] = vd;
        }
    } else if (blockIdx.x < TOKB + CNTB) {
        // ---------------- degree count (global atomics, chip-wide) --------
        int e = (blockIdx.x - TOKB) * 1024 + tid;
        if (e < ET) {
            int dst = (e < EE) ? adj[EE + e] : (e - EE);
            atomicAdd(&g_deg[dst], 1);
        }
    } else {
        // ---------------- exp LUT -----------------------------------------
        for (int k = tid; k < LUTN; k += 1024) {
            float e0 = __expf(-16.0f + (float)k       * (1.0f / LUT_SCALE));
            float e1 = __expf(-16.0f + (float)(k + 1) * (1.0f / LUT_SCALE));
            g_lut2[k] = make_float2(e0, e1);
        }
    }
}

// ------------------------------------------------------------------
// SCAN: single block; reads degrees, RESETS g_deg (graph-replay safe),
// writes exclusive offsets + fill cursors.
// ------------------------------------------------------------------
__global__ void __launch_bounds__(1024) scan_kernel() {
    __shared__ int tmp[1024];
    int t = threadIdx.x;
    int i0 = 2 * t, i1 = 2 * t + 1;
    int a = (i0 < NN) ? g_deg[i0] : 0;
    int b = (i1 < NN) ? g_deg[i1] : 0;
    if (i0 < NN) g_deg[i0] = 0;
    if (i1 < NN) g_deg[i1] = 0;
    int s = a + b;
    tmp[t] = s;
    __syncthreads();
    for (int st = 1; st < 1024; st <<= 1) {
        int u = (t >= st) ? tmp[t - st] : 0;
        __syncthreads();
        tmp[t] += u;
        __syncthreads();
    }
    int excl = tmp[t] - s;
    if (i0 < NN) { g_ofs[i0] = excl;     g_fill[i0] = excl;     }
    if (i1 < NN) { g_ofs[i1] = excl + a; g_fill[i1] = excl + a; }
    if (t == 1023) g_ofs[NN] = tmp[1023];
}

// ------------------------------------------------------------------
// SCATTER: chip-wide, global atomic fill cursors.
// ------------------------------------------------------------------
__global__ void __launch_bounds__(1024) scatter_kernel(const int* __restrict__ adj) {
    int e = blockIdx.x * 1024 + threadIdx.x;
    if (e < ET) {
        int src, dst;
        if (e < EE) { src = adj[e]; dst = adj[EE + e]; }
        else        { src = dst = e - EE; }
        int pos = atomicAdd(&g_fill[dst], 1);
        g_csr_src[pos] = src;
    }
}

// ------------------------------------------------------------------
// GAT aggregation. Block = node n x 16 graphs, 512 threads:
//   warp = one graph (wg = tid>>5), lane j = tid&31 owns 4 channels
//   [4j, 4j+4) via one LDG.128 from the fp32 token table; h = j>>3.
// smem: per (graph, edge) 4x (token, w_h) float2, edge-major so the 4
// head-addresses in a warp hit 4 distinct banks (broadcast).
// __launch_bounds__(512,4): 32 regs -> 4 blocks/SM -> 100% occupancy.
// ------------------------------------------------------------------
__global__ void __launch_bounds__(512, 4) gat_kernel(
    const int*   __restrict__ x,
    const float* __restrict__ bias,
    float*       __restrict__ out)
{
    __shared__ float2 s_tw[GPB][CAP][HH];   // 16 KB

    int tid = threadIdx.x;
    int n  = blockIdx.x >> 1;               // node
    int wg = tid >> 5;                      // warp's graph slot 0..15
    int g  = ((blockIdx.x & 1) << 4) + wg;  // graph 0..31
    int j  = tid & 31;                      // 4-channel (float4) index
    int h  = j >> 3;                        // head

    int gBase = g * NN;
    int beg = g_ofs[n];
    int deg = g_ofs[n + 1] - beg;

    int tok_d = __ldg(x + gBase + n);
    float4 ad4 = *reinterpret_cast<const float4*>(&g_tad[tok_d * HH]);

    const float4* hp = reinterpret_cast<const float4*>(g_thl) + j;

    float a0 = 0.f, a1 = 0.f, a2 = 0.f, a3 = 0.f, ssum = 0.f;

    for (int tb = 0; tb < deg; tb += CAP) {
        int cnt = min(CAP, deg - tb);

        // ---- stage: lane j stages edge j (tokens + 4 head weights) ----
        if (j < cnt) {
            int sidx = __ldg(g_csr_src + beg + tb + j);
            int tok  = __ldg(x + gBase + sidx);
            float tokf = __int_as_float(tok);
            float4 as = *reinterpret_cast<const float4*>(&g_tas[tok * HH]);
            float w[4];
#pragma unroll
            for (int q = 0; q < 4; q++) {
                float l = (q == 0) ? as.x + ad4.x : (q == 1) ? as.y + ad4.y
                        : (q == 2) ? as.z + ad4.z : as.w + ad4.w;
                l = l > 0.f ? l : NEG_SLOPE * l;
                float u = fmaf(l, LUT_SCALE, 1024.0f);    // (l+16)*64
                u = fminf(fmaxf(u, 0.0f), 2047.0f);
                int   ki = (int)u;
                float fr = u - (float)ki;
                float2 lv = __ldg(&g_lut2[ki]);
                w[q] = fmaf(fr, lv.y - lv.x, lv.x);
            }
            float4* dst = reinterpret_cast<float4*>(s_tw[wg][j]);
            dst[0] = make_float4(tokf, w[0], tokf, w[1]);
            dst[1] = make_float4(tokf, w[2], tokf, w[3]);
        }
        __syncthreads();

        // ---- gather: 1 LDS.64 + 1 LDG.128 + 4 FFMA per edge, x2 MLP ----
        int i = 0;
        for (; i + 2 <= cnt; i += 2) {
            float2 p0 = s_tw[wg][i][h];
            float2 p1 = s_tw[wg][i + 1][h];
            float4 v0 = __ldg(hp + __float_as_int(p0.x) * 32);
            float4 v1 = __ldg(hp + __float_as_int(p1.x) * 32);
            ssum += p0.y + p1.y;
            a0 = fmaf(p0.y, v0.x, a0); a1 = fmaf(p0.y, v0.y, a1);
            a2 = fmaf(p0.y, v0.z, a2); a3 = fmaf(p0.y, v0.w, a3);
            a0 = fmaf(p1.y, v1.x, a0); a1 = fmaf(p1.y, v1.y, a1);
            a2 = fmaf(p1.y, v1.z, a2); a3 = fmaf(p1.y, v1.w, a3);
        }
        if (i < cnt) {
            float2 p0 = s_tw[wg][i][h];
            float4 v0 = __ldg(hp + __float_as_int(p0.x) * 32);
            ssum += p0.y;
            a0 = fmaf(p0.y, v0.x, a0); a1 = fmaf(p0.y, v0.y, a1);
            a2 = fmaf(p0.y, v0.z, a2); a3 = fmaf(p0.y, v0.w, a3);
        }
        if (tb + CAP < deg) __syncthreads();   // uniform across block (same n)
    }

    float inv = 1.f / ssum;
    float4 bb = __ldg(reinterpret_cast<const float4*>(bias) + j);
    float4* orow = reinterpret_cast<float4*>(out + (size_t)(gBase + n) * HC) + j;
    *orow = make_float4(fmaf(a0, inv, bb.x), fmaf(a1, inv, bb.y),
                        fmaf(a2, inv, bb.z), fmaf(a3, inv, bb.w));
}

// ------------------------------------------------------------------
extern "C" void kernel_launch(void* const* d_in, const int* in_sizes, int n_in,
                              void* d_out, int out_size)
{
    const int*   x       = (const int*)  d_in[0];
    const int*   adj     = (const int*)  d_in[1];
    const float* emb     = (const float*)d_in[2];
    const float* lin_w   = (const float*)d_in[3];
    const float* att_src = (const float*)d_in[4];
    const float* att_dst = (const float*)d_in[5];
    const float* bias    = (const float*)d_in[6];
    float* out = (float*)d_out;

    prep_kernel   <<<TOKB + CNTB + 1, 1024>>>(adj, emb, lin_w, att_src, att_dst);
    scan_kernel   <<<1, 1024>>>();
    scatter_kernel<<<CNTB, 1024>>>(adj);
    gat_kernel    <<<NN * 2, 512>>>(x, bias, out);
}

// round 8
// speedup vs baseline: 1.1440x; 1.1440x over previous
#include <cuda_runtime.h>
#include <cuda_fp16.h>

// Fixed problem shapes
#define NN   2000                 // nodes per graph
#define EE   32000                // edges (before self loops)
#define ET   (EE + NN)            // 34000 edges incl. self loops
#define GG   32                   // B*D graphs
#define EMBD 32                   // embedding dim
#define HH   4                    // heads
#define HC   128                  // H*C
#define NEG_SLOPE 0.2f
#define CAP  32                   // smem edge-tile capacity (avg deg = 17)
#define TOKB (NN / 8)             // 250 token blocks
#define CNTB ((ET + 1023) / 1024) // 34 count blocks
#define XTB  ((GG * NN + 1023) / 1024) // 63 transpose blocks

// ---- scratch (device globals: no allocation allowed) ----
__device__ __half2 g_thl2[NN * 64];             // 512 KB per-TOKEN features (half2)
__device__ __align__(16) float g_tas[NN * HH];  // per-token src-logit component
__device__ __align__(16) float g_tad[NN * HH];  // per-token dst-logit component
__device__ int    g_xT[NN * GG];                // tokens transposed: [n][g]
__device__ int    g_deg[NN];                    // zero-init; scan consumes+resets
__device__ int    g_ofs[NN + 1];
__device__ int    g_fill[NN];
__device__ int    g_csr_src[ET];                // src node per CSR slot (by dst)

// exp via 2^t: deg-5 FMA polynomial + exponent bit insertion. No memory, no MUFU.
__device__ __forceinline__ float fast_exp(float v) {
    v = fminf(fmaxf(v, -80.f), 80.f);
    float t = v * 1.4426950408889634f;
    float n = rintf(t);
    float f = t - n;
    float p = 0.0013333558f;
    p = fmaf(p, f, 0.0096181291f);
    p = fmaf(p, f, 0.0555041087f);
    p = fmaf(p, f, 0.2402265069f);
    p = fmaf(p, f, 0.6931471806f);
    p = fmaf(p, f, 1.0f);
    return p * __int_as_float(((int)n + 127) << 23);
}

// ------------------------------------------------------------------
// PREP (fully parallel): token tables | degree count | x transpose.
// ------------------------------------------------------------------
__global__ void __launch_bounds__(1024) prep_kernel(
    const int*   __restrict__ x,
    const int*   __restrict__ adj,
    const float* __restrict__ emb,
    const float* __restrict__ lin_w,
    const float* __restrict__ att_src,
    const float* __restrict__ att_dst)
{
    int tid = threadIdx.x;

    if (blockIdx.x < TOKB) {
        // ---------------- token tables: 8 tokens per block ----------------
        int tok = blockIdx.x * 8 + (tid >> 7);
        int t   = tid & 127;              // output channel 0..127
        const float* er = emb + (size_t)tok * EMBD;

        float acc = 0.f;
#pragma unroll
        for (int k = 0; k < EMBD; k++)
            acc = fmaf(__ldg(er + k), __ldg(lin_w + k * HC + t), acc);

        float partner = __shfl_xor_sync(0xffffffffu, acc, 1);
        if ((t & 1) == 0)
            g_thl2[tok * 64 + (t >> 1)] = __floats2half2_rn(acc, partner);

        int lane = t & 31, h = t >> 5;
        float vs = acc * __ldg(att_src + t);
        float vd = acc * __ldg(att_dst + t);
#pragma unroll
        for (int o = 16; o > 0; o >>= 1) {
            vs += __shfl_xor_sync(0xffffffffu, vs, o);
            vd += __shfl_xor_sync(0xffffffffu, vd, o);
        }
        if (lane == 0) {
            g_tas[tok * HH + h] = vs;
            g_tad[tok * HH + h] = vd;
        }
    } else if (blockIdx.x < TOKB + CNTB) {
        // ---------------- degree count (global atomics, chip-wide) --------
        int e = (blockIdx.x - TOKB) * 1024 + tid;
        if (e < ET) {
            int dst = (e < EE) ? adj[EE + e] : (e - EE);
            atomicAdd(&g_deg[dst], 1);
        }
    } else {
        // ---------------- token transpose: x_T[n][g] = x[g][n] ------------
        int idx = (blockIdx.x - TOKB - CNTB) * 1024 + tid;
        if (idx < GG * NN) {
            int g = idx / NN, n = idx - g * NN;
            g_xT[n * GG + g] = x[idx];
        }
    }
}

// ------------------------------------------------------------------
// SCAN: single block; reads degrees, RESETS g_deg (graph-replay safe),
// writes exclusive offsets + fill cursors.
// ------------------------------------------------------------------
__global__ void __launch_bounds__(1024) scan_kernel() {
    __shared__ int tmp[1024];
    int t = threadIdx.x;
    int i0 = 2 * t, i1 = 2 * t + 1;
    int a = (i0 < NN) ? g_deg[i0] : 0;
    int b = (i1 < NN) ? g_deg[i1] : 0;
    if (i0 < NN) g_deg[i0] = 0;
    if (i1 < NN) g_deg[i1] = 0;
    int s = a + b;
    tmp[t] = s;
    __syncthreads();
    for (int st = 1; st < 1024; st <<= 1) {
        int u = (t >= st) ? tmp[t - st] : 0;
        __syncthreads();
        tmp[t] += u;
        __syncthreads();
    }
    int excl = tmp[t] - s;
    if (i0 < NN) { g_ofs[i0] = excl;     g_fill[i0] = excl;     }
    if (i1 < NN) { g_ofs[i1] = excl + a; g_fill[i1] = excl + a; }
    if (t == 1023) g_ofs[NN] = tmp[1023];
}

// ------------------------------------------------------------------
// SCATTER: chip-wide, global atomic fill cursors.
// ------------------------------------------------------------------
__global__ void __launch_bounds__(1024) scatter_kernel(const int* __restrict__ adj) {
    int e = blockIdx.x * 1024 + threadIdx.x;
    if (e < ET) {
        int src, dst;
        if (e < EE) { src = adj[e]; dst = adj[EE + e]; }
        else        { src = dst = e - EE; }
        int pos = atomicAdd(&g_fill[dst], 1);
        g_csr_src[pos] = src;
    }
}

// ------------------------------------------------------------------
// GAT aggregation. Block = node n, ALL 32 graphs, 1024 threads.
//   Gather role:  warp wg = graph, lane j owns channels [4j,4j+4) via one
//                 LDG.64 from the fp16 token table; head h = j>>3.
//   Staging role: thread (es = tid>>5, gs = tid&31) stages edge es for
//                 graph gs — x_T makes the 32-graph token load ONE
//                 coalesced 128B line per edge. Weights via fast_exp.
// smem s_tw[edge][graph][head]: stores coalesced, loads broadcast.
// __launch_bounds__(1024,2) -> 2048 thr/SM, 100% occupancy.
// ------------------------------------------------------------------
__global__ void __launch_bounds__(1024, 2) gat_kernel(
    const float* __restrict__ bias,
    float*       __restrict__ out)
{
    __shared__ float2 s_tw[CAP][GG][HH];   // 32 KB: (tok_bits, w_h)
    __shared__ float4 s_ad[GG];            // per-graph dst-logit components

    int tid = threadIdx.x;
    int n  = blockIdx.x;
    int wg = tid >> 5;                     // gather: graph  | staging: edge
    int j  = tid & 31;                     // gather: chan/4 | staging: graph
    int h  = j >> 3;

    if (tid < GG) {
        int tok_d = __ldg(g_xT + n * GG + tid);
        s_ad[tid] = *reinterpret_cast<const float4*>(&g_tad[tok_d * HH]);
    }

    int beg = g_ofs[n];
    int deg = g_ofs[n + 1] - beg;

    const float2* hp = reinterpret_cast<const float2*>(g_thl2) + j;

    float a0 = 0.f, a1 = 0.f, a2 = 0.f, a3 = 0.f, ssum = 0.f;
    __syncthreads();   // s_ad ready

    for (int tb = 0; tb < deg; tb += CAP) {
        int cnt = min(CAP, deg - tb);

        // ---- stage: thread (edge=wg, graph=j) ----
        if (wg < cnt) {
            int sidx = __ldg(g_csr_src + beg + tb + wg);     // broadcast/warp
            int tok  = __ldg(g_xT + sidx * GG + j);          // 128B coalesced
            float tokf = __int_as_float(tok);
            float4 as = *reinterpret_cast<const float4*>(&g_tas[tok * HH]);
            float4 ad = s_ad[j];
            float l0 = as.x + ad.x, l1 = as.y + ad.y;
            float l2 = as.z + ad.z, l3 = as.w + ad.w;
            l0 = l0 > 0.f ? l0 : NEG_SLOPE * l0;
            l1 = l1 > 0.f ? l1 : NEG_SLOPE * l1;
            l2 = l2 > 0.f ? l2 : NEG_SLOPE * l2;
            l3 = l3 > 0.f ? l3 : NEG_SLOPE * l3;
            float w0 = fast_exp(l0), w1 = fast_exp(l1);
            float w2 = fast_exp(l2), w3 = fast_exp(l3);
            float4* dst = reinterpret_cast<float4*>(&s_tw[wg][j][0]);
            dst[0] = make_float4(tokf, w0, tokf, w1);
            dst[1] = make_float4(tokf, w2, tokf, w3);
        }
        __syncthreads();

        // ---- gather: warp = graph wg, 1 LDS.64 + 1 LDG.64 + 5 FMA/edge ----
        int i = 0;
        for (; i + 2 <= cnt; i += 2) {
            float2 p0 = s_tw[i][wg][h];
            float2 p1 = s_tw[i + 1][wg][h];
            float2 r0 = __ldg(hp + __float_as_int(p0.x) * 32);
            float2 r1 = __ldg(hp + __float_as_int(p1.x) * 32);
            ssum += p0.y + p1.y;
            float2 u;
            u = __half22float2(*reinterpret_cast<const __half2*>(&r0.x));
            a0 = fmaf(p0.y, u.x, a0); a1 = fmaf(p0.y, u.y, a1);
            u = __half22float2(*reinterpret_cast<const __half2*>(&r0.y));
            a2 = fmaf(p0.y, u.x, a2); a3 = fmaf(p0.y, u.y, a3);
            u = __half22float2(*reinterpret_cast<const __half2*>(&r1.x));
            a0 = fmaf(p1.y, u.x, a0); a1 = fmaf(p1.y, u.y, a1);
            u = __half22float2(*reinterpret_cast<const __half2*>(&r1.y));
            a2 = fmaf(p1.y, u.x, a2); a3 = fmaf(p1.y, u.y, a3);
        }
        if (i < cnt) {
            float2 p0 = s_tw[i][wg][h];
            float2 r0 = __ldg(hp + __float_as_int(p0.x) * 32);
            ssum += p0.y;
            float2 u;
            u = __half22float2(*reinterpret_cast<const __half2*>(&r0.x));
            a0 = fmaf(p0.y, u.x, a0); a1 = fmaf(p0.y, u.y, a1);
            u = __half22float2(*reinterpret_cast<const __half2*>(&r0.y));
            a2 = fmaf(p0.y, u.x, a2); a3 = fmaf(p0.y, u.y, a3);
        }
        if (tb + CAP < deg) __syncthreads();   // uniform across block (same n)
    }

    float inv = 1.f / ssum;
    float4 bb = __ldg(reinterpret_cast<const float4*>(bias) + j);
    float4* orow = reinterpret_cast<float4*>(out + (size_t)(wg * NN + n) * HC) + j;
    *orow = make_float4(fmaf(a0, inv, bb.x), fmaf(a1, inv, bb.y),
                        fmaf(a2, inv, bb.z), fmaf(a3, inv, bb.w));
}

// ------------------------------------------------------------------
extern "C" void kernel_launch(void* const* d_in, const int* in_sizes, int n_in,
                              void* d_out, int out_size)
{
    const int*   x       = (const int*)  d_in[0];
    const int*   adj     = (const int*)  d_in[1];
    const float* emb     = (const float*)d_in[2];
    const float* lin_w   = (const float*)d_in[3];
    const float* att_src = (const float*)d_in[4];
    const float* att_dst = (const float*)d_in[5];
    const float* bias    = (const float*)d_in[6];
    float* out = (float*)d_out;

    prep_kernel   <<<TOKB + CNTB + XTB, 1024>>>(x, adj, emb, lin_w, att_src, att_dst);
    scan_kernel   <<<1, 1024>>>();
    scatter_kernel<<<CNTB, 1024>>>(adj);
    gat_kernel    <<<NN, 1024>>>(bias, out);
}

// round 10
// speedup vs baseline: 1.1894x; 1.0396x over previous
#include <cuda_runtime.h>
#include <cuda_fp16.h>

// Fixed problem shapes
#define NN   2000                 // nodes per graph
#define EE   32000                // edges (before self loops)
#define ET   (EE + NN)            // 34000 edges incl. self loops
#define GG   32                   // B*D graphs
#define EMBD 32                   // embedding dim
#define HH   4                    // heads
#define HC   128                  // H*C
#define NEG_SLOPE 0.2f
#define CAP  32                   // smem edge-tile capacity (avg deg = 17)
#define GP1  (GG + 1)             // padded graph stride (bank-conflict free)
#define TOKB (NN / 8)             // 250 token blocks
#define CNTB ((ET + 1023) / 1024) // 34 count blocks
#define XTB  ((GG * NN + 1023) / 1024) // 63 transpose blocks

// ---- scratch (device globals: no allocation allowed) ----
__device__ __half2 g_thl2[NN * 64];             // 512 KB per-TOKEN features (half2)
__device__ __align__(16) float g_tas[NN * HH];  // per-token src-logit component
__device__ __align__(16) float g_tad[NN * HH];  // per-token dst-logit component
__device__ int    g_xT[NN * GG];                // tokens transposed: [n][g]
__device__ int    g_deg[NN];                    // zero-init; scan consumes+resets
__device__ int    g_ofs[NN + 1];
__device__ int    g_fill[NN];
__device__ int    g_csr_src[ET];                // src node per CSR slot (by dst)

// exp via 2^t: deg-5 FMA polynomial + exponent bit insertion. No memory, no MUFU.
__device__ __forceinline__ float fast_exp(float v) {
    v = fminf(fmaxf(v, -80.f), 80.f);
    float t = v * 1.4426950408889634f;
    float n = rintf(t);
    float f = t - n;
    float p = 0.0013333558f;
    p = fmaf(p, f, 0.0096181291f);
    p = fmaf(p, f, 0.0555041087f);
    p = fmaf(p, f, 0.2402265069f);
    p = fmaf(p, f, 0.6931471806f);
    p = fmaf(p, f, 1.0f);
    return p * __int_as_float(((int)n + 127) << 23);
}

// ------------------------------------------------------------------
// PREP (fully parallel): token tables | degree count | x transpose.
// ------------------------------------------------------------------
__global__ void __launch_bounds__(1024) prep_kernel(
    const int*   __restrict__ x,
    const int*   __restrict__ adj,
    const float* __restrict__ emb,
    const float* __restrict__ lin_w,
    const float* __restrict__ att_src,
    const float* __restrict__ att_dst)
{
    int tid = threadIdx.x;

    if (blockIdx.x < TOKB) {
        // ---------------- token tables: 8 tokens per block ----------------
        int tok = blockIdx.x * 8 + (tid >> 7);
        int t   = tid & 127;              // output channel 0..127
        const float* er = emb + (size_t)tok * EMBD;

        float acc = 0.f;
#pragma unroll
        for (int k = 0; k < EMBD; k++)
            acc = fmaf(__ldg(er + k), __ldg(lin_w + k * HC + t), acc);

        float partner = __shfl_xor_sync(0xffffffffu, acc, 1);
        if ((t & 1) == 0)
            g_thl2[tok * 64 + (t >> 1)] = __floats2half2_rn(acc, partner);

        int lane = t & 31, h = t >> 5;
        float vs = acc * __ldg(att_src + t);
        float vd = acc * __ldg(att_dst + t);
#pragma unroll
        for (int o = 16; o > 0; o >>= 1) {
            vs += __shfl_xor_sync(0xffffffffu, vs, o);
            vd += __shfl_xor_sync(0xffffffffu, vd, o);
        }
        if (lane == 0) {
            g_tas[tok * HH + h] = vs;
            g_tad[tok * HH + h] = vd;
        }
    } else if (blockIdx.x < TOKB + CNTB) {
        // ---------------- degree count (global atomics, chip-wide) --------
        int e = (blockIdx.x - TOKB) * 1024 + tid;
        if (e < ET) {
            int dst = (e < EE) ? adj[EE + e] : (e - EE);
            atomicAdd(&g_deg[dst], 1);
        }
    } else {
        // ---------------- token transpose: x_T[n][g] = x[g][n] ------------
        int idx = (blockIdx.x - TOKB - CNTB) * 1024 + tid;
        if (idx < GG * NN) {
            int g = idx / NN, n = idx - g * NN;
            g_xT[n * GG + g] = x[idx];
        }
    }
}

// ------------------------------------------------------------------
// SCAN: single block; reads degrees, RESETS g_deg (graph-replay safe),
// writes exclusive offsets + fill cursors.
// ------------------------------------------------------------------
__global__ void __launch_bounds__(1024) scan_kernel() {
    __shared__ int tmp[1024];
    int t = threadIdx.x;
    int i0 = 2 * t, i1 = 2 * t + 1;
    int a = (i0 < NN) ? g_deg[i0] : 0;
    int b = (i1 < NN) ? g_deg[i1] : 0;
    if (i0 < NN) g_deg[i0] = 0;
    if (i1 < NN) g_deg[i1] = 0;
    int s = a + b;
    tmp[t] = s;
    __syncthreads();
    for (int st = 1; st < 1024; st <<= 1) {
        int u = (t >= st) ? tmp[t - st] : 0;
        __syncthreads();
        tmp[t] += u;
        __syncthreads();
    }
    int excl = tmp[t] - s;
    if (i0 < NN) { g_ofs[i0] = excl;     g_fill[i0] = excl;     }
    if (i1 < NN) { g_ofs[i1] = excl + a; g_fill[i1] = excl + a; }
    if (t == 1023) g_ofs[NN] = tmp[1023];
}

// ------------------------------------------------------------------
// SCATTER: chip-wide, global atomic fill cursors.
// ------------------------------------------------------------------
__global__ void __launch_bounds__(1024) scatter_kernel(const int* __restrict__ adj) {
    int e = blockIdx.x * 1024 + threadIdx.x;
    if (e < ET) {
        int src, dst;
        if (e < EE) { src = adj[e]; dst = adj[EE + e]; }
        else        { src = dst = e - EE; }
        int pos = atomicAdd(&g_fill[dst], 1);
        g_csr_src[pos] = src;
    }
}

// ------------------------------------------------------------------
// GAT aggregation. Block = node n, ALL 32 graphs, 1024 threads.
//   Gather:  warp wg = graph. Half-warp = one edge: lanes 0-15 edge i,
//            lanes 16-31 edge i+1. Lane owns 8 channels via one LDG.128
//            (address = base + staged byte-offset, no IMAD.WIDE).
//   Staging: warp = edge, lane = graph (x_T -> one 128B coalesced token
//            line per edge). Weights via fast_exp. smem split into two
//            coalesced float4 arrays (off,w0,off,w1)/(off,w2,off,w3).
//   Epilogue: parity partials combined with shfl_xor(16).
// ------------------------------------------------------------------
__global__ void __launch_bounds__(1024, 2) gat_kernel(
    const float* __restrict__ bias,
    float*       __restrict__ out)
{
    __shared__ float4 s_tw01[CAP][GP1];    // (off, w0, off, w1)
    __shared__ float4 s_tw23[CAP][GP1];    // (off, w2, off, w3)
    __shared__ float4 s_ad[GG];

    int tid  = threadIdx.x;
    int n    = blockIdx.x;
    int wg   = tid >> 5;                   // gather: graph | staging: edge
    int j    = tid & 31;                   // gather: lane  | staging: graph
    int half = j >> 4;                     // edge parity
    int k    = j & 15;                     // int4 channel index (8 ch)
    int h    = k >> 2;                     // head

    if (tid < GG) {
        int tok_d = __ldg(g_xT + n * GG + tid);
        s_ad[tid] = *reinterpret_cast<const float4*>(&g_tad[tok_d * HH]);
    }

    int beg = g_ofs[n];
    int deg = g_ofs[n + 1] - beg;

    const char* basep = reinterpret_cast<const char*>(g_thl2) + k * 16;
    // per-lane smem cursor: (array by h<2) + graph + h-parity + edge-parity
    const float2* sp = reinterpret_cast<const float2*>(h < 2 ? &s_tw01[0][0]
                                                             : &s_tw23[0][0])
                     + wg * 2 + (h & 1) + half * (GP1 * 2);

    float4 accA = make_float4(0.f, 0.f, 0.f, 0.f);
    float4 accB = make_float4(0.f, 0.f, 0.f, 0.f);
    float  ssum = 0.f;
    __syncthreads();   // s_ad ready

    for (int tb = 0; tb < deg; tb += CAP) {
        int cnt = min(CAP, deg - tb);

        // ---- stage: warp = edge wg, lane = graph j ----
        if (wg < cnt) {
            int sidx = __ldg(g_csr_src + beg + tb + wg);     // broadcast/warp
            int tok  = __ldg(g_xT + sidx * GG + j);          // 128B coalesced
            float offf = __int_as_float(tok << 8);           // byte offset
            float4 as = *reinterpret_cast<const float4*>(&g_tas[tok * HH]);
            float4 ad = s_ad[j];
            float l0 = as.x + ad.x, l1 = as.y + ad.y;
            float l2 = as.z + ad.z, l3 = as.w + ad.w;
            l0 = l0 > 0.f ? l0 : NEG_SLOPE * l0;
            l1 = l1 > 0.f ? l1 : NEG_SLOPE * l1;
            l2 = l2 > 0.f ? l2 : NEG_SLOPE * l2;
            l3 = l3 > 0.f ? l3 : NEG_SLOPE * l3;
            s_tw01[wg][j] = make_float4(offf, fast_exp(l0), offf, fast_exp(l1));
            s_tw23[wg][j] = make_float4(offf, fast_exp(l2), offf, fast_exp(l3));
        }
        __syncthreads();

        // ---- gather: per iteration 2 edges (one per half-warp) ----
        int i = 0;
#pragma unroll 2
        for (; i + 2 <= cnt; i += 2) {
            float2 p = sp[i * (GP1 * 2)];
            int4 r = __ldg(reinterpret_cast<const int4*>(basep + __float_as_int(p.x)));
            float w = p.y;
            ssum += w;
            const __half2* q = reinterpret_cast<const __half2*>(&r);
            float2 u;
            u = __half22float2(q[0]); accA.x = fmaf(w, u.x, accA.x); accA.y = fmaf(w, u.y, accA.y);
            u = __half22float2(q[1]); accA.z = fmaf(w, u.x, accA.z); accA.w = fmaf(w, u.y, accA.w);
            u = __half22float2(q[2]); accB.x = fmaf(w, u.x, accB.x); accB.y = fmaf(w, u.y, accB.y);
            u = __half22float2(q[3]); accB.z = fmaf(w, u.x, accB.z); accB.w = fmaf(w, u.y, accB.w);
        }
        if (i < cnt && half == 0) {        // odd tail: lanes 0-15 only
            float2 p = sp[i * (GP1 * 2)];
            int4 r = __ldg(reinterpret_cast<const int4*>(basep + __float_as_int(p.x)));
            float w = p.y;
            ssum += w;
            const __half2* q = reinterpret_cast<const __half2*>(&r);
            float2 u;
            u = __half22float2(q[0]); accA.x = fmaf(w, u.x, accA.x); accA.y = fmaf(w, u.y, accA.y);
            u = __half22float2(q[1]); accA.z = fmaf(w, u.x, accA.z); accA.w = fmaf(w, u.y, accA.w);
            u = __half22float2(q[2]); accB.x = fmaf(w, u.x, accB.x); accB.y = fmaf(w, u.y, accB.y);
            u = __half22float2(q[3]); accB.z = fmaf(w, u.x, accB.z); accB.w = fmaf(w, u.y, accB.w);
        }
        if (tb + CAP < deg) __syncthreads();   // uniform across block (same n)
    }

    // ---- combine edge-parity partials (same channels, lanes k <-> k+16) ----
    ssum  += __shfl_xor_sync(0xffffffffu, ssum,  16);
    accA.x += __shfl_xor_sync(0xffffffffu, accA.x, 16);
    accA.y += __shfl_xor_sync(0xffffffffu, accA.y, 16);
    accA.z += __shfl_xor_sync(0xffffffffu, accA.z, 16);
    accA.w += __shfl_xor_sync(0xffffffffu, accA.w, 16);
    accB.x += __shfl_xor_sync(0xffffffffu, accB.x, 16);
    accB.y += __shfl_xor_sync(0xffffffffu, accB.y, 16);
    accB.z += __shfl_xor_sync(0xffffffffu, accB.z, 16);
    accB.w += __shfl_xor_sync(0xffffffffu, accB.w, 16);

    if (half == 0) {
        float inv = __fdividef(1.f, ssum);
        const float4* b4 = reinterpret_cast<const float4*>(bias) + k * 2;
        float4 bb0 = __ldg(b4), bb1 = __ldg(b4 + 1);
        float4* orow = reinterpret_cast<float4*>(out + (size_t)(wg * NN + n) * HC) + k * 2;
        orow[0] = make_float4(fmaf(accA.x, inv, bb0.x), fmaf(accA.y, inv, bb0.y),
                              fmaf(accA.z, inv, bb0.z), fmaf(accA.w, inv, bb0.w));
        orow[1] = make_float4(fmaf(accB.x, inv, bb1.x), fmaf(accB.y, inv, bb1.y),
                              fmaf(accB.z, inv, bb1.z), fmaf(accB.w, inv, bb1.w));
    }
}

// ------------------------------------------------------------------
extern "C" void kernel_launch(void* const* d_in, const int* in_sizes, int n_in,
                              void* d_out, int out_size)
{
    const int*   x       = (const int*)  d_in[0];
    const int*   adj     = (const int*)  d_in[1];
    const float* emb     = (const float*)d_in[2];
    const float* lin_w   = (const float*)d_in[3];
    const float* att_src = (const float*)d_in[4];
    const float* att_dst = (const float*)d_in[5];
    const float* bias    = (const float*)d_in[6];
    float* out = (float*)d_out;

    prep_kernel   <<<TOKB + CNTB + XTB, 1024>>>(x, adj, emb, lin_w, att_src, att_dst);
    scan_kernel   <<<1, 1024>>>();
    scatter_kernel<<<CNTB, 1024>>>(adj);
    gat_kernel    <<<NN, 1024>>>(bias, out);
}

// round 11
// speedup vs baseline: 1.2211x; 1.0267x over previous
#include <cuda_runtime.h>
#include <cuda_fp16.h>

// Fixed problem shapes
#define NN   2000                 // nodes per graph
#define EE   32000                // edges (before self loops)
#define ET   (EE + NN)            // 34000 edges incl. self loops
#define GG   32                   // B*D graphs
#define EMBD 32                   // embedding dim
#define HH   4                    // heads
#define HC   128                  // H*C
#define NEG_SLOPE 0.2f
#define CAP  32                   // smem edge-tile capacity (avg deg = 17)
#define GP1  (GG + 1)             // padded graph stride
#define ELLW 64                   // ELL row capacity (P(deg>64) ~ 0 for Poisson(16))
#define TOKB (NN / 8)             // 250 token blocks
#define ELLB ((ET + 1023) / 1024) // 34 ELL-build blocks
#define XTB  ((GG * NN + 1023) / 1024) // 63 transpose blocks

// ---- scratch (device globals: no allocation allowed) ----
__device__ __half2 g_thl2[NN * 64];             // 512 KB per-TOKEN features (half2)
__device__ __align__(16) float g_tas[NN * HH];  // per-token src-logit component
__device__ __align__(16) float g_tad[NN * HH];  // per-token dst-logit component
__device__ int    g_xT[NN * GG];                // tokens transposed: [n][g]
__device__ int    g_cnt[NN];                    // ELL fill counts (zero-init; gat resets)
__device__ int    g_ell[NN * ELLW];             // ELL src lists (by dst)

// exp(v) * 2^-6 via 2^t: deg-5 FMA polynomial + exponent bit insertion.
// The -6 bias rides the existing FMA (free); it guards fp16 products
// against overflow and cancels in acc/ssum.
__device__ __forceinline__ float fast_exp_s(float v) {
    v = fminf(fmaxf(v, -80.f), 80.f);
    float t = fmaf(v, 1.4426950408889634f, -6.0f);
    float n = rintf(t);
    float f = t - n;
    float p = 0.0013333558f;
    p = fmaf(p, f, 0.0096181291f);
    p = fmaf(p, f, 0.0555041087f);
    p = fmaf(p, f, 0.2402265069f);
    p = fmaf(p, f, 0.6931471806f);
    p = fmaf(p, f, 1.0f);
    return p * __int_as_float(((int)n + 127) << 23);
}

// ------------------------------------------------------------------
// PREP (one kernel, fully parallel):
//   blocks [0, TOKB)            : per-token tables
//   blocks [TOKB, TOKB+ELLB)    : ELL build (atomic append per dst)
//   blocks [TOKB+ELLB, +XTB)    : token transpose x_T[n][g]
// ------------------------------------------------------------------
__global__ void __launch_bounds__(1024) prep_kernel(
    const int*   __restrict__ x,
    const int*   __restrict__ adj,
    const float* __restrict__ emb,
    const float* __restrict__ lin_w,
    const float* __restrict__ att_src,
    const float* __restrict__ att_dst)
{
    int tid = threadIdx.x;

    if (blockIdx.x < TOKB) {
        // ---------------- token tables: 8 tokens per block ----------------
        int tok = blockIdx.x * 8 + (tid >> 7);
        int t   = tid & 127;              // output channel 0..127
        const float* er = emb + (size_t)tok * EMBD;

        float acc = 0.f;
#pragma unroll
        for (int k = 0; k < EMBD; k++)
            acc = fmaf(__ldg(er + k), __ldg(lin_w + k * HC + t), acc);

        float partner = __shfl_xor_sync(0xffffffffu, acc, 1);
        if ((t & 1) == 0)
            g_thl2[tok * 64 + (t >> 1)] = __floats2half2_rn(acc, partner);

        int lane = t & 31, h = t >> 5;
        float vs = acc * __ldg(att_src + t);
        float vd = acc * __ldg(att_dst + t);
#pragma unroll
        for (int o = 16; o > 0; o >>= 1) {
            vs += __shfl_xor_sync(0xffffffffu, vs, o);
            vd += __shfl_xor_sync(0xffffffffu, vd, o);
        }
        if (lane == 0) {
            g_tas[tok * HH + h] = vs;
            g_tad[tok * HH + h] = vd;
        }
    } else if (blockIdx.x < TOKB + ELLB) {
        // ---------------- ELL build (atomic append) -----------------------
        int e = (blockIdx.x - TOKB) * 1024 + tid;
        if (e < ET) {
            int src, dst;
            if (e < EE) { src = adj[e]; dst = adj[EE + e]; }
            else        { src = dst = e - EE; }
            int pos = atomicAdd(&g_cnt[dst], 1);
            g_ell[dst * ELLW + pos] = src;
        }
    } else {
        // ---------------- token transpose: x_T[n][g] = x[g][n] ------------
        int idx = (blockIdx.x - TOKB - ELLB) * 1024 + tid;
        if (idx < GG * NN) {
            int g = idx / NN, n = idx - g * NN;
            g_xT[n * GG + g] = x[idx];
        }
    }
}

// ------------------------------------------------------------------
// GAT aggregation. Block = node n, ALL 32 graphs, 1024 threads.
//   Gather:  warp wg = graph. Half-warp parity: lanes 0-15 even edges,
//            16-31 odd edges. Each lane accumulates 2 edges at a time in
//            HALF2 (HMUL2+HFMA2), converting to fp32 once per pair.
//            Lane owns 8 channels via one LDG.128 per edge.
//   Staging: warp = edge, lane = graph; x_T gives one coalesced 128B
//            token line per edge. Weights via fast_exp_s (scaled 2^-6).
//   The block owning node n resets g_cnt[n] for the next graph replay.
// ------------------------------------------------------------------
__global__ void __launch_bounds__(1024, 2) gat_kernel(
    const float* __restrict__ bias,
    float*       __restrict__ out)
{
    __shared__ float4 s_tw01[CAP][GP1];    // (off, w0, off, w1)
    __shared__ float4 s_tw23[CAP][GP1];    // (off, w2, off, w3)
    __shared__ float4 s_ad[GG];

    int tid  = threadIdx.x;
    int n    = blockIdx.x;
    int wg   = tid >> 5;                   // gather: graph | staging: edge
    int j    = tid & 31;                   // gather: lane  | staging: graph
    int half = j >> 4;                     // edge parity
    int k    = j & 15;                     // int4 channel index (8 ch)
    int h    = k >> 2;                     // head

    if (tid < GG) {
        int tok_d = __ldg(g_xT + n * GG + tid);
        s_ad[tid] = *reinterpret_cast<const float4*>(&g_tad[tok_d * HH]);
    }

    int deg = g_cnt[n];                    // read BEFORE the barrier
    int ebase = n * ELLW;

    const char* basep = reinterpret_cast<const char*>(g_thl2) + k * 16;
    const float2* sp = reinterpret_cast<const float2*>(h < 2 ? &s_tw01[0][0]
                                                             : &s_tw23[0][0])
                     + wg * 2 + (h & 1);

    float4 accA = make_float4(0.f, 0.f, 0.f, 0.f);
    float4 accB = make_float4(0.f, 0.f, 0.f, 0.f);
    float  ssum = 0.f;
    __syncthreads();                       // s_ad ready; all deg reads done
    if (tid == 0) g_cnt[n] = 0;            // reset for next replay

    for (int tb = 0; tb < deg; tb += CAP) {
        int cnt = min(CAP, deg - tb);

        // ---- stage: warp = edge wg, lane = graph j ----
        if (wg < cnt) {
            int sidx = __ldg(g_ell + ebase + tb + wg);       // broadcast/warp
            int tok  = __ldg(g_xT + sidx * GG + j);          // 128B coalesced
            float offf = __int_as_float(tok << 8);           // byte offset
            float4 as = *reinterpret_cast<const float4*>(&g_tas[tok * HH]);
            float4 ad = s_ad[j];
            float l0 = as.x + ad.x, l1 = as.y + ad.y;
            float l2 = as.z + ad.z, l3 = as.w + ad.w;
            l0 = l0 > 0.f ? l0 : NEG_SLOPE * l0;
            l1 = l1 > 0.f ? l1 : NEG_SLOPE * l1;
            l2 = l2 > 0.f ? l2 : NEG_SLOPE * l2;
            l3 = l3 > 0.f ? l3 : NEG_SLOPE * l3;
            s_tw01[wg][j] = make_float4(offf, fast_exp_s(l0), offf, fast_exp_s(l1));
            s_tw23[wg][j] = make_float4(offf, fast_exp_s(l2), offf, fast_exp_s(l3));
        }
        __syncthreads();

        // ---- gather: lane processes 2 same-parity edges per iter in half2 ----
        int i = half;
        for (; i + 2 < cnt; i += 4) {
            float2 pA = sp[i * (GP1 * 2)];
            float2 pB = sp[(i + 2) * (GP1 * 2)];
            int4 rA = __ldg(reinterpret_cast<const int4*>(basep + __float_as_int(pA.x)));
            int4 rB = __ldg(reinterpret_cast<const int4*>(basep + __float_as_int(pB.x)));
            ssum += pA.y + pB.y;
            __half2 whA = __float2half2_rn(pA.y);
            __half2 whB = __float2half2_rn(pB.y);
            const __half2* qA = reinterpret_cast<const __half2*>(&rA);
            const __half2* qB = reinterpret_cast<const __half2*>(&rB);
            __half2 h0 = __hmul2(whA, qA[0]);
            __half2 h1 = __hmul2(whA, qA[1]);
            __half2 h2 = __hmul2(whA, qA[2]);
            __half2 h3 = __hmul2(whA, qA[3]);
            h0 = __hfma2(whB, qB[0], h0);
            h1 = __hfma2(whB, qB[1], h1);
            h2 = __hfma2(whB, qB[2], h2);
            h3 = __hfma2(whB, qB[3], h3);
            float2 u;
            u = __half22float2(h0); accA.x += u.x; accA.y += u.y;
            u = __half22float2(h1); accA.z += u.x; accA.w += u.y;
            u = __half22float2(h2); accB.x += u.x; accB.y += u.y;
            u = __half22float2(h3); accB.z += u.x; accB.w += u.y;
        }
        for (; i < cnt; i += 2) {          // parity tail (<=1 iter)
            float2 pA = sp[i * (GP1 * 2)];
            int4 rA = __ldg(reinterpret_cast<const int4*>(basep + __float_as_int(pA.x)));
            ssum += pA.y;
            __half2 whA = __float2half2_rn(pA.y);
            const __half2* qA = reinterpret_cast<const __half2*>(&rA);
            float2 u;
            u = __half22float2(__hmul2(whA, qA[0])); accA.x += u.x; accA.y += u.y;
            u = __half22float2(__hmul2(whA, qA[1])); accA.z += u.x; accA.w += u.y;
            u = __half22float2(__hmul2(whA, qA[2])); accB.x += u.x; accB.y += u.y;
            u = __half22float2(__hmul2(whA, qA[3])); accB.z += u.x; accB.w += u.y;
        }
        if (tb + CAP < deg) __syncthreads();   // uniform across block (same n)
    }

    // ---- combine edge-parity partials (lanes k <-> k+16) ----
    ssum   += __shfl_xor_sync(0xffffffffu, ssum,   16);
    accA.x += __shfl_xor_sync(0xffffffffu, accA.x, 16);
    accA.y += __shfl_xor_sync(0xffffffffu, accA.y, 16);
    accA.z += __shfl_xor_sync(0xffffffffu, accA.z, 16);
    accA.w += __shfl_xor_sync(0xffffffffu, accA.w, 16);
    accB.x += __shfl_xor_sync(0xffffffffu, accB.x, 16);
    accB.y += __shfl_xor_sync(0xffffffffu, accB.y, 16);
    accB.z += __shfl_xor_sync(0xffffffffu, accB.z, 16);
    accB.w += __shfl_xor_sync(0xffffffffu, accB.w, 16);

    if (half == 0) {
        float inv = __fdividef(1.f, ssum);     // 2^-6 scale cancels here
        const float4* b4 = reinterpret_cast<const float4*>(bias) + k * 2;
        float4 bb0 = __ldg(b4), bb1 = __ldg(b4 + 1);
        float4* orow = reinterpret_cast<float4*>(out + (size_t)(wg * NN + n) * HC) + k * 2;
        orow[0] = make_float4(fmaf(accA.x, inv, bb0.x), fmaf(accA.y, inv, bb0.y),
                              fmaf(accA.z, inv, bb0.z), fmaf(accA.w, inv, bb0.w));
        orow[1] = make_float4(fmaf(accB.x, inv, bb1.x), fmaf(accB.y, inv, bb1.y),
                              fmaf(accB.z, inv, bb1.z), fmaf(accB.w, inv, bb1.w));
    }
}

// ------------------------------------------------------------------
extern "C" void kernel_launch(void* const* d_in, const int* in_sizes, int n_in,
                              void* d_out, int out_size)
{
    const int*   x       = (const int*)  d_in[0];
    const int*   adj     = (const int*)  d_in[1];
    const float* emb     = (const float*)d_in[2];
    const float* lin_w   = (const float*)d_in[3];
    const float* att_src = (const float*)d_in[4];
    const float* att_dst = (const float*)d_in[5];
    const float* bias    = (const float*)d_in[6];
    float* out = (float*)d_out;

    prep_kernel<<<TOKB + ELLB + XTB, 1024>>>(x, adj, emb, lin_w, att_src, att_dst);
    gat_kernel <<<NN, 1024>>>(bias, out);
}

// round 12
// speedup vs baseline: 1.3039x; 1.0678x over previous
#include <cuda_runtime.h>
#include <cuda_fp16.h>

// Fixed problem shapes
#define NN   2000                 // nodes per graph
#define EE   32000                // edges (before self loops)
#define ET   (EE + NN)            // 34000 edges incl. self loops
#define GG   32                   // B*D graphs
#define EMBD 32                   // embedding dim
#define HH   4                    // heads
#define HC   128                  // H*C
#define NEG_SLOPE 0.2f
#define GP1  (GG + 1)             // padded graph stride
#define ELLW 64                   // ELL row capacity (P(deg>64) ~ 1e-19, Poisson(16))
#define TOKB (NN / 8)             // 250 token blocks
#define ELLB ((ET + 1023) / 1024) // 34 ELL-build blocks
#define XTB  ((GG * NN + 1023) / 1024) // 63 transpose blocks

// ---- scratch (device globals: no allocation allowed) ----
__device__ __half2 g_thl2[NN * 64];             // 512 KB per-TOKEN features (half2)
__device__ __align__(16) float g_tas[NN * HH];  // per-token src-logit component
__device__ __align__(16) float g_tad[NN * HH];  // per-token dst-logit component
__device__ int    g_xT[NN * GG];                // tokens transposed: [n][g]
__device__ int    g_cnt[NN];                    // ELL fill counts (zero-init; gat resets)
__device__ int    g_ell[NN * ELLW];             // ELL src lists (by dst)

// exp via 2^t: deg-5 FMA polynomial + exponent bit insertion. No memory, no MUFU.
__device__ __forceinline__ float fast_exp(float v) {
    v = fminf(fmaxf(v, -80.f), 80.f);
    float t = v * 1.4426950408889634f;
    float n = rintf(t);
    float f = t - n;
    float p = 0.0013333558f;
    p = fmaf(p, f, 0.0096181291f);
    p = fmaf(p, f, 0.0555041087f);
    p = fmaf(p, f, 0.2402265069f);
    p = fmaf(p, f, 0.6931471806f);
    p = fmaf(p, f, 1.0f);
    return p * __int_as_float(((int)n + 127) << 23);
}

// ------------------------------------------------------------------
// PREP (one kernel, fully parallel):
//   [0, TOKB)         : per-token tables
//   [TOKB, +ELLB)     : ELL build (atomic append per dst)
//   [TOKB+ELLB, +XTB) : token transpose x_T[n][g]
// ------------------------------------------------------------------
__global__ void __launch_bounds__(1024) prep_kernel(
    const int*   __restrict__ x,
    const int*   __restrict__ adj,
    const float* __restrict__ emb,
    const float* __restrict__ lin_w,
    const float* __restrict__ att_src,
    const float* __restrict__ att_dst)
{
    int tid = threadIdx.x;

    if (blockIdx.x < TOKB) {
        // ---------------- token tables: 8 tokens per block ----------------
        int tok = blockIdx.x * 8 + (tid >> 7);
        int t   = tid & 127;              // output channel 0..127
        const float* er = emb + (size_t)tok * EMBD;

        float acc = 0.f;
#pragma unroll
        for (int k = 0; k < EMBD; k++)
            acc = fmaf(__ldg(er + k), __ldg(lin_w + k * HC + t), acc);

        float partner = __shfl_xor_sync(0xffffffffu, acc, 1);
        if ((t & 1) == 0)
            g_thl2[tok * 64 + (t >> 1)] = __floats2half2_rn(acc, partner);

        int lane = t & 31, h = t >> 5;
        float vs = acc * __ldg(att_src + t);
        float vd = acc * __ldg(att_dst + t);
#pragma unroll
        for (int o = 16; o > 0; o >>= 1) {
            vs += __shfl_xor_sync(0xffffffffu, vs, o);
            vd += __shfl_xor_sync(0xffffffffu, vd, o);
        }
        if (lane == 0) {
            g_tas[tok * HH + h] = vs;
            g_tad[tok * HH + h] = vd;
        }
    } else if (blockIdx.x < TOKB + ELLB) {
        // ---------------- ELL build (atomic append, bounds-guarded) -------
        int e = (blockIdx.x - TOKB) * 1024 + tid;
        if (e < ET) {
            int src, dst;
            if (e < EE) { src = adj[e]; dst = adj[EE + e]; }
            else        { src = dst = e - EE; }
            int pos = atomicAdd(&g_cnt[dst], 1);
            if (pos < ELLW) g_ell[dst * ELLW + pos] = src;
        }
    } else {
        // ---------------- token transpose: x_T[n][g] = x[g][n] ------------
        int idx = (blockIdx.x - TOKB - ELLB) * 1024 + tid;
        if (idx < GG * NN) {
            int g = idx / NN, n = idx - g * NN;
            g_xT[n * GG + g] = x[idx];
        }
    }
}

// ------------------------------------------------------------------
// GAT aggregation. Block = node n, ALL 32 graphs, 1024 threads.
//   Staging: ALL deg (<=64) edges staged once (warp = edge, lane = graph;
//            x_T -> one coalesced 128B token line per edge). ONE barrier.
//   Gather:  warp wg = graph; half-warp = edge parity; lane owns 8
//            channels via LDG.128 (address = base + staged byte-offset).
//   Epilogue: parity partials combined with shfl_xor(16).
// smem ~68 KB -> 2 blocks/SM (attribute opt-in), 2048 thr/SM = 100% occ.
// ------------------------------------------------------------------
__global__ void __launch_bounds__(1024, 2) gat_kernel(
    const float* __restrict__ bias,
    float*       __restrict__ out)
{
    __shared__ float4 s_tw01[ELLW][GP1];   // (off, w0, off, w1)
    __shared__ float4 s_tw23[ELLW][GP1];   // (off, w2, off, w3)
    __shared__ float4 s_ad[GG];

    int tid  = threadIdx.x;
    int n    = blockIdx.x;
    int wg   = tid >> 5;                   // gather: graph | staging: edge
    int j    = tid & 31;                   // gather: lane  | staging: graph
    int half = j >> 4;                     // edge parity
    int k    = j & 15;                     // int4 channel index (8 ch)
    int h    = k >> 2;                     // head

    if (tid < GG) {
        int tok_d = __ldg(g_xT + n * GG + tid);
        s_ad[tid] = *reinterpret_cast<const float4*>(&g_tad[tok_d * HH]);
    }

    int deg = min(g_cnt[n], ELLW);         // read BEFORE the barrier
    int ebase = n * ELLW;

    const char* basep = reinterpret_cast<const char*>(g_thl2) + k * 16;
    const float2* sp = reinterpret_cast<const float2*>(h < 2 ? &s_tw01[0][0]
                                                             : &s_tw23[0][0])
                     + wg * 2 + (h & 1) + half * (GP1 * 2);

    float4 accA = make_float4(0.f, 0.f, 0.f, 0.f);
    float4 accB = make_float4(0.f, 0.f, 0.f, 0.f);
    float  ssum = 0.f;
    __syncthreads();                       // s_ad ready; all deg reads done
    if (tid == 0) g_cnt[n] = 0;            // reset for next graph replay

    // ---- stage ALL edges once: warp = edge e (e = wg, wg+32) ----
#pragma unroll
    for (int e = wg; e < deg; e += 32) {
        int sidx = __ldg(g_ell + ebase + e);             // broadcast/warp
        int tok  = __ldg(g_xT + sidx * GG + j);          // 128B coalesced
        float offf = __int_as_float(tok << 8);           // byte offset
        float4 as = *reinterpret_cast<const float4*>(&g_tas[tok * HH]);
        float4 ad = s_ad[j];
        float l0 = as.x + ad.x, l1 = as.y + ad.y;
        float l2 = as.z + ad.z, l3 = as.w + ad.w;
        l0 = l0 > 0.f ? l0 : NEG_SLOPE * l0;
        l1 = l1 > 0.f ? l1 : NEG_SLOPE * l1;
        l2 = l2 > 0.f ? l2 : NEG_SLOPE * l2;
        l3 = l3 > 0.f ? l3 : NEG_SLOPE * l3;
        s_tw01[e][j] = make_float4(offf, fast_exp(l0), offf, fast_exp(l1));
        s_tw23[e][j] = make_float4(offf, fast_exp(l2), offf, fast_exp(l3));
    }
    __syncthreads();

    // ---- gather: 2 edges per iteration (one per half-warp), no barriers ----
    int i = 0;
#pragma unroll 2
    for (; i + 2 <= deg; i += 2) {
        float2 p = sp[i * (GP1 * 2)];
        int4 r = __ldg(reinterpret_cast<const int4*>(basep + __float_as_int(p.x)));
        float w = p.y;
        ssum += w;
        const __half2* q = reinterpret_cast<const __half2*>(&r);
        float2 u;
        u = __half22float2(q[0]); accA.x = fmaf(w, u.x, accA.x); accA.y = fmaf(w, u.y, accA.y);
        u = __half22float2(q[1]); accA.z = fmaf(w, u.x, accA.z); accA.w = fmaf(w, u.y, accA.w);
        u = __half22float2(q[2]); accB.x = fmaf(w, u.x, accB.x); accB.y = fmaf(w, u.y, accB.y);
        u = __half22float2(q[3]); accB.z = fmaf(w, u.x, accB.z); accB.w = fmaf(w, u.y, accB.w);
    }
    if (i < deg && half == 0) {            // odd tail: lanes 0-15 only
        float2 p = sp[i * (GP1 * 2)];
        int4 r = __ldg(reinterpret_cast<const int4*>(basep + __float_as_int(p.x)));
        float w = p.y;
        ssum += w;
        const __half2* q = reinterpret_cast<const __half2*>(&r);
        float2 u;
        u = __half22float2(q[0]); accA.x = fmaf(w, u.x, accA.x); accA.y = fmaf(w, u.y, accA.y);
        u = __half22float2(q[1]); accA.z = fmaf(w, u.x, accA.z); accA.w = fmaf(w, u.y, accA.w);
        u = __half22float2(q[2]); accB.x = fmaf(w, u.x, accB.x); accB.y = fmaf(w, u.y, accB.y);
        u = __half22float2(q[3]); accB.z = fmaf(w, u.x, accB.z); accB.w = fmaf(w, u.y, accB.w);
    }

    // ---- combine edge-parity partials (lanes k <-> k+16) ----
    ssum   += __shfl_xor_sync(0xffffffffu, ssum,   16);
    accA.x += __shfl_xor_sync(0xffffffffu, accA.x, 16);
    accA.y += __shfl_xor_sync(0xffffffffu, accA.y, 16);
    accA.z += __shfl_xor_sync(0xffffffffu, accA.z, 16);
    accA.w += __shfl_xor_sync(0xffffffffu, accA.w, 16);
    accB.x += __shfl_xor_sync(0xffffffffu, accB.x, 16);
    accB.y += __shfl_xor_sync(0xffffffffu, accB.y, 16);
    accB.z += __shfl_xor_sync(0xffffffffu, accB.z, 16);
    accB.w += __shfl_xor_sync(0xffffffffu, accB.w, 16);

    if (half == 0) {
        float inv = __fdividef(1.f, ssum);
        const float4* b4 = reinterpret_cast<const float4*>(bias) + k * 2;
        float4 bb0 = __ldg(b4), bb1 = __ldg(b4 + 1);
        float4* orow = reinterpret_cast<float4*>(out + (size_t)(wg * NN + n) * HC) + k * 2;
        orow[0] = make_float4(fmaf(accA.x, inv, bb0.x), fmaf(accA.y, inv, bb0.y),
                              fmaf(accA.z, inv, bb0.z), fmaf(accA.w, inv, bb0.w));
        orow[1] = make_float4(fmaf(accB.x, inv, bb1.x), fmaf(accB.y, inv, bb1.y),
                              fmaf(accB.z, inv, bb1.z), fmaf(accB.w, inv, bb1.w));
    }
}

// ------------------------------------------------------------------
extern "C" void kernel_launch(void* const* d_in, const int* in_sizes, int n_in,
                              void* d_out, int out_size)
{
    const int*   x       = (const int*)  d_in[0];
    const int*   adj     = (const int*)  d_in[1];
    const float* emb     = (const float*)d_in[2];
    const float* lin_w   = (const float*)d_in[3];
    const float* att_src = (const float*)d_in[4];
    const float* att_dst = (const float*)d_in[5];
    const float* bias    = (const float*)d_in[6];
    float* out = (float*)d_out;

    // ~68 KB static smem needs the opt-in (host-side, capture-safe)
    static bool attr_done = false;
    if (!attr_done) {
        cudaFuncSetAttribute(gat_kernel,
                             cudaFuncAttributeMaxDynamicSharedMemorySize, 0);
        attr_done = true;
    }

    prep_kernel<<<TOKB + ELLB + XTB, 1024>>>(x, adj, emb, lin_w, att_src, att_dst);
    gat_kernel <<<NN, 1024>>>(bias, out);
}

// round 13
// speedup vs baseline: 1.3431x; 1.0300x over previous
#include <cuda_runtime.h>
#include <cuda_fp16.h>

// Fixed problem shapes
#define NN   2000                 // nodes per graph
#define EE   32000                // edges (before self loops)
#define ET   (EE + NN)            // 34000 edges incl. self loops
#define GG   32                   // B*D graphs
#define EMBD 32                   // embedding dim
#define HH   4                    // heads
#define HC   128                  // H*C
#define NEG_SLOPE 0.2f
#define GP1  (GG + 1)             // padded graph stride
#define ELLW 64                   // ELL row capacity (P(deg>64) ~ 1e-19, Poisson(16))
#define TOKB (NN / 8)             // 250 token blocks
#define ELLB ((ET + 1023) / 1024) // 34 ELL-build blocks
#define XTB  ((GG * NN + 1023) / 1024) // 63 transpose blocks

// ---- scratch (device globals: no allocation allowed) ----
__device__ __half2 g_thl2[NN * 64];             // 512 KB per-TOKEN features (half2)
__device__ __align__(16) float g_tas[NN * HH];  // per-token src-logit component
__device__ __align__(16) float g_tad[NN * HH];  // per-token dst-logit component
__device__ int    g_xT[NN * GG];                // tokens transposed: [n][g]
__device__ int    g_cnt[NN];                    // ELL fill counts (zero-init; gat resets)
__device__ int    g_ell[NN * ELLW];             // ELL src lists (by dst)

// exp(v) * 2^-6 via 2^t: deg-5 FMA polynomial + exponent bit insertion.
// The -6 bias rides the existing FMA (free); it guards fp16 products/sums
// against overflow and cancels in acc/ssum.
__device__ __forceinline__ float fast_exp_s(float v) {
    v = fminf(fmaxf(v, -80.f), 80.f);
    float t = fmaf(v, 1.4426950408889634f, -6.0f);
    float n = rintf(t);
    float f = t - n;
    float p = 0.0013333558f;
    p = fmaf(p, f, 0.0096181291f);
    p = fmaf(p, f, 0.0555041087f);
    p = fmaf(p, f, 0.2402265069f);
    p = fmaf(p, f, 0.6931471806f);
    p = fmaf(p, f, 1.0f);
    return p * __int_as_float(((int)n + 127) << 23);
}

// ------------------------------------------------------------------
// PREP (one kernel, fully parallel):
//   [0, TOKB)         : per-token tables
//   [TOKB, +ELLB)     : ELL build (atomic append per dst)
//   [TOKB+ELLB, +XTB) : token transpose x_T[n][g]
// ------------------------------------------------------------------
__global__ void __launch_bounds__(1024) prep_kernel(
    const int*   __restrict__ x,
    const int*   __restrict__ adj,
    const float* __restrict__ emb,
    const float* __restrict__ lin_w,
    const float* __restrict__ att_src,
    const float* __restrict__ att_dst)
{
    int tid = threadIdx.x;

    if (blockIdx.x < TOKB) {
        // ---------------- token tables: 8 tokens per block ----------------
        int tok = blockIdx.x * 8 + (tid >> 7);
        int t   = tid & 127;              // output channel 0..127
        const float* er = emb + (size_t)tok * EMBD;

        float acc = 0.f;
#pragma unroll
        for (int k = 0; k < EMBD; k++)
            acc = fmaf(__ldg(er + k), __ldg(lin_w + k * HC + t), acc);

        float partner = __shfl_xor_sync(0xffffffffu, acc, 1);
        if ((t & 1) == 0)
            g_thl2[tok * 64 + (t >> 1)] = __floats2half2_rn(acc, partner);

        int lane = t & 31, h = t >> 5;
        float vs = acc * __ldg(att_src + t);
        float vd = acc * __ldg(att_dst + t);
#pragma unroll
        for (int o = 16; o > 0; o >>= 1) {
            vs += __shfl_xor_sync(0xffffffffu, vs, o);
            vd += __shfl_xor_sync(0xffffffffu, vd, o);
        }
        if (lane == 0) {
            g_tas[tok * HH + h] = vs;
            g_tad[tok * HH + h] = vd;
        }
    } else if (blockIdx.x < TOKB + ELLB) {
        // ---------------- ELL build (atomic append, bounds-guarded) -------
        int e = (blockIdx.x - TOKB) * 1024 + tid;
        if (e < ET) {
            int src, dst;
            if (e < EE) { src = adj[e]; dst = adj[EE + e]; }
            else        { src = dst = e - EE; }
            int pos = atomicAdd(&g_cnt[dst], 1);
            if (pos < ELLW) g_ell[dst * ELLW + pos] = src;
        }
    } else {
        // ---------------- token transpose: x_T[n][g] = x[g][n] ------------
        int idx = (blockIdx.x - TOKB - ELLB) * 1024 + tid;
        if (idx < GG * NN) {
            int g = idx / NN, n = idx - g * NN;
            g_xT[n * GG + g] = x[idx];
        }
    }
}

// ------------------------------------------------------------------
// GAT aggregation. Block = node n, ALL 32 graphs, 1024 threads.
//   Staging: ALL deg (<=64) edges staged once (warp = edge, lane = graph;
//            x_T -> one coalesced 128B token line per edge). ONE barrier.
//   Gather:  warp wg = graph; half-warp = edge parity; lane owns 8
//            channels via LDG.128. Accumulation in HALF2 (HFMA2, scaled
//            weights) flushed to fp32 every 8-edge chunk -> ~2.5x fewer
//            math instructions than scalar cvt+FFMA.
//   Epilogue: parity partials combined with shfl_xor(16).
// ------------------------------------------------------------------
__global__ void __launch_bounds__(1024, 2) gat_kernel(
    const float* __restrict__ bias,
    float*       __restrict__ out)
{
    __shared__ float4 s_tw01[ELLW][GP1];   // (off, w0, off, w1)
    __shared__ float4 s_tw23[ELLW][GP1];   // (off, w2, off, w3)
    __shared__ float4 s_ad[GG];

    int tid  = threadIdx.x;
    int n    = blockIdx.x;
    int wg   = tid >> 5;                   // gather: graph | staging: edge
    int j    = tid & 31;                   // gather: lane  | staging: graph
    int half = j >> 4;                     // edge parity
    int k    = j & 15;                     // int4 channel index (8 ch)
    int h    = k >> 2;                     // head

    if (tid < GG) {
        int tok_d = __ldg(g_xT + n * GG + tid);
        s_ad[tid] = *reinterpret_cast<const float4*>(&g_tad[tok_d * HH]);
    }

    int deg = min(g_cnt[n], ELLW);         // read BEFORE the barrier
    int ebase = n * ELLW;

    const char* basep = reinterpret_cast<const char*>(g_thl2) + k * 16;
    const float2* sp = reinterpret_cast<const float2*>(h < 2 ? &s_tw01[0][0]
                                                             : &s_tw23[0][0])
                     + wg * 2 + (h & 1) + half * (GP1 * 2);

    float4 accA = make_float4(0.f, 0.f, 0.f, 0.f);
    float4 accB = make_float4(0.f, 0.f, 0.f, 0.f);
    float  ssum = 0.f;
    __syncthreads();                       // s_ad ready; all deg reads done
    if (tid == 0) g_cnt[n] = 0;            // reset for next graph replay

    // ---- stage ALL edges once: warp = edge e (e = wg, wg+32) ----
#pragma unroll
    for (int e = wg; e < deg; e += 32) {
        int sidx = __ldg(g_ell + ebase + e);             // broadcast/warp
        int tok  = __ldg(g_xT + sidx * GG + j);          // 128B coalesced
        float offf = __int_as_float(tok << 8);           // byte offset
        float4 as = *reinterpret_cast<const float4*>(&g_tas[tok * HH]);
        float4 ad = s_ad[j];
        float l0 = as.x + ad.x, l1 = as.y + ad.y;
        float l2 = as.z + ad.z, l3 = as.w + ad.w;
        l0 = l0 > 0.f ? l0 : NEG_SLOPE * l0;
        l1 = l1 > 0.f ? l1 : NEG_SLOPE * l1;
        l2 = l2 > 0.f ? l2 : NEG_SLOPE * l2;
        l3 = l3 > 0.f ? l3 : NEG_SLOPE * l3;
        s_tw01[e][j] = make_float4(offf, fast_exp_s(l0), offf, fast_exp_s(l1));
        s_tw23[e][j] = make_float4(offf, fast_exp_s(l2), offf, fast_exp_s(l3));
    }
    __syncthreads();

    // ---- gather: half2 accumulation, flush every 8-edge chunk ----
    const __half2 hz = __float2half2_rn(0.f);
    int i = 0;

    while (i + 8 <= deg) {                 // full chunk: 4 pairs, no branches
        __half2 h0 = hz, h1 = hz, h2 = hz, h3 = hz;
#pragma unroll
        for (int u = 0; u < 4; u++) {
            float2 p = sp[(i + 2 * u) * (GP1 * 2)];
            int4 r = __ldg(reinterpret_cast<const int4*>(basep + __float_as_int(p.x)));
            ssum += p.y;
            __half2 wh = __float2half2_rn(p.y);
            const __half2* q = reinterpret_cast<const __half2*>(&r);
            h0 = __hfma2(wh, q[0], h0);
            h1 = __hfma2(wh, q[1], h1);
            h2 = __hfma2(wh, q[2], h2);
            h3 = __hfma2(wh, q[3], h3);
        }
        float2 u2;
        u2 = __half22float2(h0); accA.x += u2.x; accA.y += u2.y;
        u2 = __half22float2(h1); accA.z += u2.x; accA.w += u2.y;
        u2 = __half22float2(h2); accB.x += u2.x; accB.y += u2.y;
        u2 = __half22float2(h3); accB.z += u2.x; accB.w += u2.y;
        i += 8;
    }

    {   // remainder: <4 pairs + possible odd edge (chain still <= 4)
        __half2 h0 = hz, h1 = hz, h2 = hz, h3 = hz;
        for (; i + 2 <= deg; i += 2) {
            float2 p = sp[i * (GP1 * 2)];
            int4 r = __ldg(reinterpret_cast<const int4*>(basep + __float_as_int(p.x)));
            ssum += p.y;
            __half2 wh = __float2half2_rn(p.y);
            const __half2* q = reinterpret_cast<const __half2*>(&r);
            h0 = __hfma2(wh, q[0], h0);
            h1 = __hfma2(wh, q[1], h1);
            h2 = __hfma2(wh, q[2], h2);
            h3 = __hfma2(wh, q[3], h3);
        }
        if (i < deg && half == 0) {        // odd final edge: lanes 0-15 only
            float2 p = sp[i * (GP1 * 2)];
            int4 r = __ldg(reinterpret_cast<const int4*>(basep + __float_as_int(p.x)));
            ssum += p.y;
            __half2 wh = __float2half2_rn(p.y);
            const __half2* q = reinterpret_cast<const __half2*>(&r);
            h0 = __hfma2(wh, q[0], h0);
            h1 = __hfma2(wh, q[1], h1);
            h2 = __hfma2(wh, q[2], h2);
            h3 = __hfma2(wh, q[3], h3);
        }
        float2 u2;
        u2 = __half22float2(h0); accA.x += u2.x; accA.y += u2.y;
        u2 = __half22float2(h1); accA.z += u2.x; accA.w += u2.y;
        u2 = __half22float2(h2); accB.x += u2.x; accB.y += u2.y;
        u2 = __half22float2(h3); accB.z += u2.x; accB.w += u2.y;
    }

    // ---- combine edge-parity partials (lanes k <-> k+16) ----
    ssum   += __shfl_xor_sync(0xffffffffu, ssum,   16);
    accA.x += __shfl_xor_sync(0xffffffffu, accA.x, 16);
    accA.y += __shfl_xor_sync(0xffffffffu, accA.y, 16);
    accA.z += __shfl_xor_sync(0xffffffffu, accA.z, 16);
    accA.w += __shfl_xor_sync(0xffffffffu, accA.w, 16);
    accB.x += __shfl_xor_sync(0xffffffffu, accB.x, 16);
    accB.y += __shfl_xor_sync(0xffffffffu, accB.y, 16);
    accB.z += __shfl_xor_sync(0xffffffffu, accB.z, 16);
    accB.w += __shfl_xor_sync(0xffffffffu, accB.w, 16);

    if (half == 0) {
        float inv = __fdividef(1.f, ssum);     // 2^-6 scale cancels here
        const float4* b4 = reinterpret_cast<const float4*>(bias) + k * 2;
        float4 bb0 = __ldg(b4), bb1 = __ldg(b4 + 1);
        float4* orow = reinterpret_cast<float4*>(out + (size_t)(wg * NN + n) * HC) + k * 2;
        orow[0] = make_float4(fmaf(accA.x, inv, bb0.x), fmaf(accA.y, inv, bb0.y),
                              fmaf(accA.z, inv, bb0.z), fmaf(accA.w, inv, bb0.w));
        orow[1] = make_float4(fmaf(accB.x, inv, bb1.x), fmaf(accB.y, inv, bb1.y),
                              fmaf(accB.z, inv, bb1.z), fmaf(accB.w, inv, bb1.w));
    }
}

// ------------------------------------------------------------------
extern "C" void kernel_launch(void* const* d_in, const int* in_sizes, int n_in,
                              void* d_out, int out_size)
{
    const int*   x       = (const int*)  d_in[0];
    const int*   adj     = (const int*)  d_in[1];
    const float* emb     = (const float*)d_in[2];
    const float* lin_w   = (const float*)d_in[3];
    const float* att_src = (const float*)d_in[4];
    const float* att_dst = (const float*)d_in[5];
    const float* bias    = (const float*)d_in[6];
    float* out = (float*)d_out;

    prep_kernel<<<TOKB + ELLB + XTB, 1024>>>(x, adj, emb, lin_w, att_src, att_dst);
    gat_kernel <<<NN, 1024>>>(bias, out);
}